// round 9
// baseline (speedup 1.0000x reference)
#include <cuda_runtime.h>
#include <cuda_bf16.h>
#include <cstdint>

// Problem constants
#define Bz 32
#define Lz 512
#define Hz 256
#define ML (Bz*Lz)          // 16384 rows

// ---------------- device scratch ----------------
__device__ float g_Hq[ML*Hz];
__device__ float g_Pp[ML*Hz];
__device__ float g_scores[Bz*Lz*Lz];     // reused in-place as attn
__device__ float g_PC[ML*2*Hz];          // [P | C] concat
__device__ float g_Cg[ML*Hz];            // gated context
__device__ float g_gilT[Lz*3*Hz*Bz];     // [t][g*256+j][b]
__device__ float g_girT[Lz*3*Hz*Bz];
__device__ float g_ht[2][2][Hz*Bz];      // [dir][buf][j*32+b]  (transposed h)
__device__ unsigned g_bar[2];

// ---------------- helpers ----------------
__device__ __forceinline__ float tanh_fast(float x) {
    float y; asm("tanh.approx.f32 %0, %1;" : "=f"(y) : "f"(x)); return y;
}
__device__ __forceinline__ float sigmoidf_(float x) {
    return 1.0f / (1.0f + __expf(-x));
}
__device__ __forceinline__ unsigned ld_acq(const unsigned* p) {
    unsigned v; asm volatile("ld.acquire.gpu.global.u32 %0, [%1];" : "=r"(v) : "l"(p)); return v;
}
__device__ __forceinline__ void red_release_add(unsigned* p, unsigned v) {
    asm volatile("red.release.gpu.global.add.u32 [%0], %1;" :: "l"(p), "r"(v) : "memory");
}
__device__ __forceinline__ unsigned f2tf32(float x) {
    unsigned r; asm("cvt.rna.tf32.f32 %0, %1;" : "=r"(r) : "f"(x)); return r;
}
__device__ __forceinline__ void mma_tf32(float c[4], const unsigned a[4], unsigned b0, unsigned b1) {
    asm volatile("mma.sync.aligned.m16n8k8.row.col.f32.tf32.tf32.f32 "
        "{%0,%1,%2,%3},{%4,%5,%6,%7},{%8,%9},{%0,%1,%2,%3};"
        : "+f"(c[0]), "+f"(c[1]), "+f"(c[2]), "+f"(c[3])
        : "r"(a[0]), "r"(a[1]), "r"(a[2]), "r"(a[3]), "r"(b0), "r"(b1));
}

// ---------------- tensor-core GEMM (tf32) ----------------
// C[M,N] = A[M,K] @ op(B) ; TRANSB=1: B is N x K row-major (use B^T);
//                           TRANSB=0: B is K x N row-major.
// EPI 0: +bias ; EPI 1: sigmoid(acc+bias)*aux[row*512+256+col] ; EPI 2: plain
// EPI 3: +bias, scatter to giT layout [(t*768+col)*32+b], row = b*512+t
#define PADK 20

template<int EPI>
__device__ __forceinline__ void epi_store(float v, int row, int col,
    const float* __restrict__ bias, const float* __restrict__ aux,
    float* __restrict__ Cc, long cbase, int ldc, int coff)
{
    if (EPI == 0) {
        Cc[cbase + (long)row * ldc + coff + col] = v + bias[col];
    } else if (EPI == 1) {
        float g = sigmoidf_(v + bias[col]);
        Cc[cbase + (long)row * ldc + coff + col] = g * aux[(long)row * 512 + 256 + col];
    } else if (EPI == 2) {
        Cc[cbase + (long)row * ldc + coff + col] = v;
    } else {
        float vv = v + bias[col];
        int b = row >> 9, t = row & 511;
        Cc[((long)t * 768 + col) * 32 + b] = vv;
    }
}

template<int TRANSB, int EPI>
__global__ void __launch_bounds__(256) mma_gemm_kernel(
    const float* __restrict__ A, const float* __restrict__ Bm,
    const float* __restrict__ bias, const float* __restrict__ aux,
    float* __restrict__ Cc,
    int M, int N, int K,
    long sA, long sB, long sC, int ldc, int coff)
{
    __shared__ unsigned As[128 * PADK];
    __shared__ unsigned Bs[128 * PADK];
    int z = blockIdx.z;
    A  += z * sA;
    Bm += z * sB;
    long cbase = (long)z * sC;
    int m0 = blockIdx.y * 128, n0 = blockIdx.x * 128;
    int tid = threadIdx.x;
    int wid = tid >> 5, lane = tid & 31;
    int g = lane >> 2, tg = lane & 3;
    int warp_m = (wid & 3) * 32, warp_n = (wid >> 2) * 64;

    float acc[2][8][4];
#pragma unroll
    for (int mt = 0; mt < 2; mt++)
#pragma unroll
        for (int nt = 0; nt < 8; nt++)
#pragma unroll
            for (int q = 0; q < 4; q++) acc[mt][nt][q] = 0.f;

    int arow = tid >> 2;          // 0..63
    int akk  = (tid & 3) * 4;     // 0,4,8,12
    int nloc = tid & 127;         // TRANSB=0 staging
    int kseg = (tid >> 7) * 8;

    for (int k0 = 0; k0 < K; k0 += 16) {
        // A tile -> As[m][k], stride PADK
        {
            float4 a0 = *(const float4*)&A[(long)(m0 + arow) * K + k0 + akk];
            float4 a1 = *(const float4*)&A[(long)(m0 + arow + 64) * K + k0 + akk];
            unsigned* d0 = &As[arow * PADK + akk];
            d0[0] = f2tf32(a0.x); d0[1] = f2tf32(a0.y); d0[2] = f2tf32(a0.z); d0[3] = f2tf32(a0.w);
            unsigned* d1 = &As[(arow + 64) * PADK + akk];
            d1[0] = f2tf32(a1.x); d1[1] = f2tf32(a1.y); d1[2] = f2tf32(a1.z); d1[3] = f2tf32(a1.w);
        }
        // B tile -> Bs[n][k], stride PADK
        if (TRANSB) {
            float4 b0 = *(const float4*)&Bm[(long)(n0 + arow) * K + k0 + akk];
            float4 b1 = *(const float4*)&Bm[(long)(n0 + arow + 64) * K + k0 + akk];
            unsigned* d0 = &Bs[arow * PADK + akk];
            d0[0] = f2tf32(b0.x); d0[1] = f2tf32(b0.y); d0[2] = f2tf32(b0.z); d0[3] = f2tf32(b0.w);
            unsigned* d1 = &Bs[(arow + 64) * PADK + akk];
            d1[0] = f2tf32(b1.x); d1[1] = f2tf32(b1.y); d1[2] = f2tf32(b1.z); d1[3] = f2tf32(b1.w);
        } else {
            float tv[8];
#pragma unroll
            for (int kk = 0; kk < 8; kk++)
                tv[kk] = Bm[(long)(k0 + kseg + kk) * N + n0 + nloc];
            unsigned* d = &Bs[nloc * PADK + kseg];
#pragma unroll
            for (int kk = 0; kk < 8; kk++) d[kk] = f2tf32(tv[kk]);
        }
        __syncthreads();
#pragma unroll
        for (int ks = 0; ks < 16; ks += 8) {
            unsigned afr[2][4];
#pragma unroll
            for (int mt = 0; mt < 2; mt++) {
                int mb = warp_m + mt * 16;
                afr[mt][0] = As[(mb + g    ) * PADK + ks + tg];
                afr[mt][1] = As[(mb + g + 8) * PADK + ks + tg];
                afr[mt][2] = As[(mb + g    ) * PADK + ks + tg + 4];
                afr[mt][3] = As[(mb + g + 8) * PADK + ks + tg + 4];
            }
#pragma unroll
            for (int nt = 0; nt < 8; nt++) {
                int nb = warp_n + nt * 8;
                unsigned b0 = Bs[(nb + g) * PADK + ks + tg];
                unsigned b1 = Bs[(nb + g) * PADK + ks + tg + 4];
                mma_tf32(acc[0][nt], afr[0], b0, b1);
                mma_tf32(acc[1][nt], afr[1], b0, b1);
            }
        }
        __syncthreads();
    }
    // epilogue
#pragma unroll
    for (int mt = 0; mt < 2; mt++) {
        int r0 = m0 + warp_m + mt * 16 + g;
        int r1 = r0 + 8;
#pragma unroll
        for (int nt = 0; nt < 8; nt++) {
            int c0 = n0 + warp_n + nt * 8 + 2 * tg;
            epi_store<EPI>(acc[mt][nt][0], r0, c0,     bias, aux, Cc, cbase, ldc, coff);
            epi_store<EPI>(acc[mt][nt][1], r0, c0 + 1, bias, aux, Cc, cbase, ldc, coff);
            epi_store<EPI>(acc[mt][nt][2], r1, c0,     bias, aux, Cc, cbase, ldc, coff);
            epi_store<EPI>(acc[mt][nt][3], r1, c0 + 1, bias, aux, Cc, cbase, ldc, coff);
        }
    }
}

// ---------------- copy P into PC[:, :256] ----------------
__global__ void copyP_kernel(const float* __restrict__ P, float* __restrict__ PC) {
    int i = blockIdx.x * blockDim.x + threadIdx.x;
    int r = i >> 6;
    int c4 = i & 63;
    ((float4*)PC)[(long)r * 128 + c4] = ((const float4*)P)[i];
}

// ---------------- scores ----------------
__global__ void __launch_bounds__(256) scores_kernel(
    const float* __restrict__ Hq, const float* __restrict__ Pp,
    const float* __restrict__ ws_w, const float* __restrict__ ws_b,
    float* __restrict__ scores)
{
    __shared__ float pp[8][256];
    __shared__ float wss[256];
    int b = blockIdx.y;
    int t0 = blockIdx.x * 8;
    int tid = threadIdx.x;
    for (int idx = tid; idx < 8 * 256; idx += 256) {
        int tt = idx >> 8, h = idx & 255;
        pp[tt][h] = Pp[((long)(b * 512 + t0 + tt)) * 256 + h];
    }
    if (tid < 256) wss[tid] = ws_w[tid];
    __syncthreads();
    float wsb = __ldg(ws_b);
    int warp = tid >> 5, lane = tid & 31;
    float wsr[8];
#pragma unroll
    for (int u = 0; u < 8; u++) wsr[u] = wss[lane * 8 + u];

    for (int l = warp; l < 512; l += 8) {
        const float4* hp = (const float4*)(Hq + ((long)(b * 512 + l)) * 256 + lane * 8);
        float4 ha = hp[0], hb = hp[1];
        float hv[8] = {ha.x, ha.y, ha.z, ha.w, hb.x, hb.y, hb.z, hb.w};
        float accv[8];
#pragma unroll
        for (int tt = 0; tt < 8; tt++) {
            const float4* pq = (const float4*)&pp[tt][lane * 8];
            float4 pa = pq[0], pb = pq[1];
            float pv[8] = {pa.x, pa.y, pa.z, pa.w, pb.x, pb.y, pb.z, pb.w};
            float s = 0.f;
#pragma unroll
            for (int u = 0; u < 8; u++)
                s = fmaf(tanh_fast(hv[u] + pv[u]), wsr[u], s);
            accv[tt] = s;
        }
#pragma unroll
        for (int off = 16; off; off >>= 1)
#pragma unroll
            for (int tt = 0; tt < 8; tt++)
                accv[tt] += __shfl_xor_sync(0xffffffffu, accv[tt], off);
        if (lane < 8)
            scores[((long)(b * 512 + t0 + lane)) * 512 + l] = accv[lane] + wsb;
    }
}

// ---------------- softmax ----------------
__global__ void __launch_bounds__(256) softmax_kernel(float* __restrict__ s) {
    int row = blockIdx.x * 8 + (threadIdx.x >> 5);
    int lane = threadIdx.x & 31;
    float* p = s + (long)row * 512;
    float v[16];
    float m = -1e30f;
#pragma unroll
    for (int u = 0; u < 16; u++) { v[u] = p[u * 32 + lane]; m = fmaxf(m, v[u]); }
#pragma unroll
    for (int off = 16; off; off >>= 1) m = fmaxf(m, __shfl_xor_sync(0xffffffffu, m, off));
    float sum = 0.f;
#pragma unroll
    for (int u = 0; u < 16; u++) { v[u] = __expf(v[u] - m); sum += v[u]; }
#pragma unroll
    for (int off = 16; off; off >>= 1) sum += __shfl_xor_sync(0xffffffffu, sum, off);
    float inv = 1.0f / sum;
#pragma unroll
    for (int u = 0; u < 16; u++) p[u * 32 + lane] = v[u] * inv;
}

// ---------------- init recurrence state ----------------
__global__ void init_kernel() {
    int i = blockIdx.x * blockDim.x + threadIdx.x;
    if (i < 2 * 2 * Hz * Bz) ((float*)g_ht)[i] = 0.f;
    if (i < 2) g_bar[i] = 0u;
}

// ---------------- recurrence: 128 blocks (2 dirs x 64), 128 thr, warp=j lane=b ----
__global__ void __launch_bounds__(128, 1) recur_kernel(
    const float* __restrict__ Whh_l, const float* __restrict__ bhh_l,
    const float* __restrict__ Whh_r, const float* __restrict__ bhh_r,
    float* __restrict__ out)
{
    __shared__ float ht[Hz * Bz];          // [k][b], 32KB
    __shared__ float wsm[4 * 3 * 256];     // [jl][g][k], 12KB

    int dir   = blockIdx.x >> 6;
    int slice = blockIdx.x & 63;
    int tid   = threadIdx.x;
    int warp  = tid >> 5, lane = tid & 31;
    int j = slice * 4 + warp;

    const float* Whh = dir ? Whh_r : Whh_l;
    const float* bhh = dir ? bhh_r : bhh_l;
    const float* giT = dir ? g_girT : g_gilT;

    for (int idx = tid; idx < 3072; idx += 128) {
        int jl  = idx / 768;
        int rem = idx - jl * 768;
        int g   = rem >> 8;
        int k   = rem & 255;
        wsm[idx] = Whh[((g << 8) + slice * 4 + jl) * 256 + k];
    }
    float br = bhh[j], bz = bhh[j + 256], bn = bhh[j + 512];
    const float* wp = &wsm[warp * 768];

    unsigned* bar = &g_bar[dir];

    for (int s = 0; s < 512; s++) {
        int t = dir ? (511 - s) : s;
        const float4* hsrc = (const float4*)(&g_ht[dir][s & 1][0]);
#pragma unroll
        for (int i = 0; i < 16; i++)
            ((float4*)ht)[tid + i * 128] = __ldcg(&hsrc[tid + i * 128]);
        __syncthreads();

        float sr0 = 0.f, sz0 = 0.f, sn0 = 0.f;
        float sr1 = 0.f, sz1 = 0.f, sn1 = 0.f;
#pragma unroll 8
        for (int k = 0; k < 256; k += 4) {
            float h0 = ht[(k + 0) * 32 + lane];
            float h1 = ht[(k + 1) * 32 + lane];
            float h2 = ht[(k + 2) * 32 + lane];
            float h3 = ht[(k + 3) * 32 + lane];
            float4 wr = *(const float4*)&wp[k];
            float4 wz = *(const float4*)&wp[256 + k];
            float4 wn = *(const float4*)&wp[512 + k];
            sr0 = fmaf(wr.x, h0, sr0); sr1 = fmaf(wr.y, h1, sr1);
            sr0 = fmaf(wr.z, h2, sr0); sr1 = fmaf(wr.w, h3, sr1);
            sz0 = fmaf(wz.x, h0, sz0); sz1 = fmaf(wz.y, h1, sz1);
            sz0 = fmaf(wz.z, h2, sz0); sz1 = fmaf(wz.w, h3, sz1);
            sn0 = fmaf(wn.x, h0, sn0); sn1 = fmaf(wn.y, h1, sn1);
            sn0 = fmaf(wn.z, h2, sn0); sn1 = fmaf(wn.w, h3, sn1);
        }
        float sr = sr0 + sr1, sz = sz0 + sz1, sn = sn0 + sn1;

        long gbase = ((long)t * 768 + j) * 32 + lane;
        float gr_ = __ldg(giT + gbase);
        float gz_ = __ldg(giT + gbase + 256 * 32);
        float gn_ = __ldg(giT + gbase + 512 * 32);
        float hprev = ht[j * 32 + lane];
        float r = sigmoidf_(gr_ + br + sr);
        float z = sigmoidf_(gz_ + bz + sz);
        float n = tanh_fast(gn_ + r * (bn + sn));
        float hnew = (1.0f - z) * n + z * hprev;
        __stcg(&g_ht[dir][(s + 1) & 1][j * 32 + lane], hnew);
        out[((long)(lane * 512 + t)) * 512 + dir * 256 + j] = hnew;

        __syncthreads();
        if (tid == 0) {
            red_release_add(bar, 1u);
            unsigned target = 64u * (unsigned)(s + 1);
            while (ld_acq(bar) < target) { }
        }
        __syncthreads();
    }
}

// ---------------- host launcher ----------------
extern "C" void kernel_launch(void* const* d_in, const int* in_sizes, int n_in,
                              void* d_out, int out_size) {
    const float* P     = (const float*)d_in[0];
    const float* wq_w  = (const float*)d_in[1];
    const float* wq_b  = (const float*)d_in[2];
    const float* wp_w  = (const float*)d_in[3];
    const float* wp_b  = (const float*)d_in[4];
    const float* ws_w  = (const float*)d_in[5];
    const float* ws_b  = (const float*)d_in[6];
    const float* wg_w  = (const float*)d_in[7];
    const float* wg_b  = (const float*)d_in[8];
    const float* Wih_l = (const float*)d_in[9];
    const float* Whh_l = (const float*)d_in[10];
    const float* bih_l = (const float*)d_in[11];
    const float* bhh_l = (const float*)d_in[12];
    const float* Wih_r = (const float*)d_in[13];
    const float* Whh_r = (const float*)d_in[14];
    const float* bih_r = (const float*)d_in[15];
    const float* bhh_r = (const float*)d_in[16];
    float* out = (float*)d_out;

    float *pHq, *pPp, *pScores, *pPC, *pCg, *pGilT, *pGirT;
    cudaGetSymbolAddress((void**)&pHq, g_Hq);
    cudaGetSymbolAddress((void**)&pPp, g_Pp);
    cudaGetSymbolAddress((void**)&pScores, g_scores);
    cudaGetSymbolAddress((void**)&pPC, g_PC);
    cudaGetSymbolAddress((void**)&pCg, g_Cg);
    cudaGetSymbolAddress((void**)&pGilT, g_gilT);
    cudaGetSymbolAddress((void**)&pGirT, g_girT);

    // Phase A (all GEMMs tf32 tensor cores)
    mma_gemm_kernel<1,0><<<dim3(2,128,1), 256>>>(P, wq_w, wq_b, nullptr, pHq,
        ML, 256, 256, 0, 0, 0, 256, 0);
    mma_gemm_kernel<1,0><<<dim3(2,128,1), 256>>>(P, wp_w, wp_b, nullptr, pPp,
        ML, 256, 256, 0, 0, 0, 256, 0);
    copyP_kernel<<<ML*256/4/256, 256>>>(P, pPC);
    scores_kernel<<<dim3(64,32), 256>>>(pHq, pPp, ws_w, ws_b, pScores);
    softmax_kernel<<<ML/8, 256>>>(pScores);
    // context per-b: C = attn @ P -> PC[:, 256:512]
    mma_gemm_kernel<0,2><<<dim3(2,4,32), 256>>>(pScores, P, nullptr, nullptr, pPC,
        512, 256, 512, (long)512*512, (long)512*256, (long)512*512, 512, 256);
    // gate: Cg = sigmoid(PC @ wg^T + b) * C
    mma_gemm_kernel<1,1><<<dim3(2,128,1), 256>>>(pPC, wg_w, wg_b, pPC, pCg,
        ML, 256, 512, 0, 0, 0, 256, 0);
    // GRU input projections -> transposed giT layout
    mma_gemm_kernel<1,3><<<dim3(6,128,1), 256>>>(pCg, Wih_l, bih_l, nullptr, pGilT,
        ML, 768, 256, 0, 0, 0, 0, 0);
    mma_gemm_kernel<1,3><<<dim3(6,128,1), 256>>>(pCg, Wih_r, bih_r, nullptr, pGirT,
        ML, 768, 256, 0, 0, 0, 0, 0);

    // Phase B
    init_kernel<<<128, 256>>>();
    recur_kernel<<<128, 128>>>(Whh_l, bhh_l, Whh_r, bhh_r, out);
}

// round 13
// speedup vs baseline: 1.3089x; 1.3089x over previous
#include <cuda_runtime.h>
#include <cuda_bf16.h>
#include <cstdint>

typedef unsigned long long ull;

// Problem constants
#define Bz 32
#define Lz 512
#define Hz 256
#define ML (Bz*Lz)          // 16384 rows

// ---------------- device scratch ----------------
__device__ float g_Hq[ML*Hz];
__device__ float g_Pp[ML*Hz];
__device__ float g_scores[Bz*Lz*Lz];     // reused in-place as attn
__device__ float g_PC[ML*2*Hz];          // [P | C] concat
__device__ float g_Cg[ML*Hz];            // gated context
__device__ float g_gilT[Lz*3*Hz*Bz];     // [t][g*256+j][b]
__device__ float g_girT[Lz*3*Hz*Bz];
__device__ float g_ht[2][2][Hz*Bz];      // [dir][buf], pair-interleaved: (k>>1)*64 + b*2 + (k&1)
__device__ unsigned g_bar[2];

// ---------------- helpers ----------------
__device__ __forceinline__ float tanh_fast(float x) {
    float y; asm("tanh.approx.f32 %0, %1;" : "=f"(y) : "f"(x)); return y;
}
__device__ __forceinline__ float sigmoidf_(float x) {
    return 1.0f / (1.0f + __expf(-x));
}
__device__ __forceinline__ unsigned ld_acq(const unsigned* p) {
    unsigned v; asm volatile("ld.acquire.gpu.global.u32 %0, [%1];" : "=r"(v) : "l"(p)); return v;
}
__device__ __forceinline__ void red_release_add(unsigned* p, unsigned v) {
    asm volatile("red.release.gpu.global.add.u32 [%0], %1;" :: "l"(p), "r"(v) : "memory");
}
// packed f32x2 FMA: c.lo += a.lo*b.lo ; c.hi += a.hi*b.hi
__device__ __forceinline__ void ffma2(ull& c, ull a, ull b) {
    asm("fma.rn.f32x2 %0, %1, %2, %0;" : "+l"(c) : "l"(a), "l"(b));
}
__device__ __forceinline__ ull dup2(float v) {
    ull r; asm("mov.b64 %0, {%1, %1};" : "=l"(r) : "f"(v)); return r;
}
__device__ __forceinline__ float2 unp2(ull v) {
    float2 r; asm("mov.b64 {%0, %1}, %2;" : "=f"(r.x), "=f"(r.y) : "l"(v)); return r;
}

// ---------------- f32x2 SGEMM ----------------
// C[M,N] = A[M,K] @ op(B).  TRANSB=1: B is N x K row-major (A@B^T).
//                           TRANSB=0: B is K x N row-major.
// EPI 0: +bias ; EPI 1: sigmoid(acc+bias)*aux[row*512+256+col] ; EPI 2: plain
// EPI 3: +bias, scatter to giT layout [(t*768+col)*32+b], row = b*512+t
#define BMt 128
#define BNt 128
#define BKt 16
#define BNP 129    // Bs2 row stride in ull (pad 1)

template<int EPI>
__device__ __forceinline__ void epi_store(float v, int row, int col,
    const float* __restrict__ bias, const float* __restrict__ aux,
    float* __restrict__ Cc, long cbase, int ldc, int coff)
{
    if (EPI == 0) {
        Cc[cbase + (long)row * ldc + coff + col] = v + bias[col];
    } else if (EPI == 1) {
        float g = sigmoidf_(v + bias[col]);
        Cc[cbase + (long)row * ldc + coff + col] = g * aux[(long)row * 512 + 256 + col];
    } else if (EPI == 2) {
        Cc[cbase + (long)row * ldc + coff + col] = v;
    } else {
        float vv = v + bias[col];
        int b = row >> 9, t = row & 511;
        Cc[((long)t * 768 + col) * 32 + b] = vv;
    }
}

template<int TRANSB, int EPI>
__global__ void __launch_bounds__(256, 2) sgemm2_kernel(
    const float* __restrict__ A, const float* __restrict__ Bm,
    const float* __restrict__ bias, const float* __restrict__ aux,
    float* __restrict__ Cc,
    int M, int N, int K,
    long sA, long sB, long sC, int ldc, int coff)
{
    __shared__ float As[BKt][BMt];
    __shared__ ull   Bs2[BKt][BNP];
    int z = blockIdx.z;
    A  += z * sA;
    Bm += z * sB;
    long cbase = (long)z * sC;
    int m0 = blockIdx.y * BMt, n0 = blockIdx.x * BNt;
    int tid = threadIdx.x;
    int tr = tid >> 4, tc = tid & 15;

    int arow = tid >> 2;          // 0..63
    int akk  = (tid & 3) * 4;     // 0,4,8,12
    int nloc = tid & 127;         // TRANSB=0 staging
    int kseg = (tid >> 7) * 8;

    // acc2[p][jj] = packed rows (m0+tr*8+2p, +1), col n0 + tc + 16*jj
    ull acc2[4][8];
#pragma unroll
    for (int p = 0; p < 4; p++)
#pragma unroll
        for (int jj = 0; jj < 8; jj++) acc2[p][jj] = 0ull;

    for (int k0 = 0; k0 < K; k0 += BKt) {
        // A tile -> As[k][m]
        {
            float4 a0 = *(const float4*)&A[(long)(m0 + arow) * K + k0 + akk];
            float4 a1 = *(const float4*)&A[(long)(m0 + arow + 64) * K + k0 + akk];
            As[akk+0][arow] = a0.x; As[akk+1][arow] = a0.y; As[akk+2][arow] = a0.z; As[akk+3][arow] = a0.w;
            As[akk+0][arow+64] = a1.x; As[akk+1][arow+64] = a1.y; As[akk+2][arow+64] = a1.z; As[akk+3][arow+64] = a1.w;
        }
        // B tile -> Bs2[k][n] duplicated pairs
        if (TRANSB) {
            float4 b0 = *(const float4*)&Bm[(long)(n0 + arow) * K + k0 + akk];
            float4 b1 = *(const float4*)&Bm[(long)(n0 + arow + 64) * K + k0 + akk];
            Bs2[akk+0][arow] = dup2(b0.x); Bs2[akk+1][arow] = dup2(b0.y);
            Bs2[akk+2][arow] = dup2(b0.z); Bs2[akk+3][arow] = dup2(b0.w);
            Bs2[akk+0][arow+64] = dup2(b1.x); Bs2[akk+1][arow+64] = dup2(b1.y);
            Bs2[akk+2][arow+64] = dup2(b1.z); Bs2[akk+3][arow+64] = dup2(b1.w);
        } else {
            float tv[8];
#pragma unroll
            for (int kk = 0; kk < 8; kk++)
                tv[kk] = Bm[(long)(k0 + kseg + kk) * N + n0 + nloc];
#pragma unroll
            for (int kk = 0; kk < 8; kk++)
                Bs2[kseg + kk][nloc] = dup2(tv[kk]);
        }
        __syncthreads();
#pragma unroll
        for (int kk = 0; kk < BKt; kk++) {
            ulonglong2 av0 = *(const ulonglong2*)&As[kk][tr*8];     // (m0,m1),(m2,m3)
            ulonglong2 av1 = *(const ulonglong2*)&As[kk][tr*8+4];   // (m4,m5),(m6,m7)
            ull b2[8];
#pragma unroll
            for (int jj = 0; jj < 8; jj++) b2[jj] = Bs2[kk][tc + 16*jj];
#pragma unroll
            for (int jj = 0; jj < 8; jj++) {
                ffma2(acc2[0][jj], av0.x, b2[jj]);
                ffma2(acc2[1][jj], av0.y, b2[jj]);
                ffma2(acc2[2][jj], av1.x, b2[jj]);
                ffma2(acc2[3][jj], av1.y, b2[jj]);
            }
        }
        __syncthreads();
    }
    // epilogue
#pragma unroll
    for (int p = 0; p < 4; p++) {
        int r0 = m0 + tr*8 + 2*p;
#pragma unroll
        for (int jj = 0; jj < 8; jj++) {
            int col = n0 + tc + 16*jj;
            float2 c = unp2(acc2[p][jj]);
            epi_store<EPI>(c.x, r0,     col, bias, aux, Cc, cbase, ldc, coff);
            epi_store<EPI>(c.y, r0 + 1, col, bias, aux, Cc, cbase, ldc, coff);
        }
    }
}

// ---------------- copy P into PC[:, :256] ----------------
__global__ void copyP_kernel(const float* __restrict__ P, float* __restrict__ PC) {
    int i = blockIdx.x * blockDim.x + threadIdx.x;
    int r = i >> 6;
    int c4 = i & 63;
    ((float4*)PC)[(long)r * 128 + c4] = ((const float4*)P)[i];
}

// ---------------- scores ----------------
__global__ void __launch_bounds__(256) scores_kernel(
    const float* __restrict__ Hq, const float* __restrict__ Pp,
    const float* __restrict__ ws_w, const float* __restrict__ ws_b,
    float* __restrict__ scores)
{
    __shared__ float pp[8][256];
    __shared__ float wss[256];
    int b = blockIdx.y;
    int t0 = blockIdx.x * 8;
    int tid = threadIdx.x;
    for (int idx = tid; idx < 8 * 256; idx += 256) {
        int tt = idx >> 8, h = idx & 255;
        pp[tt][h] = Pp[((long)(b * 512 + t0 + tt)) * 256 + h];
    }
    if (tid < 256) wss[tid] = ws_w[tid];
    __syncthreads();
    float wsb = __ldg(ws_b);
    int warp = tid >> 5, lane = tid & 31;
    float wsr[8];
#pragma unroll
    for (int u = 0; u < 8; u++) wsr[u] = wss[lane * 8 + u];

    for (int l = warp; l < 512; l += 8) {
        const float4* hp = (const float4*)(Hq + ((long)(b * 512 + l)) * 256 + lane * 8);
        float4 ha = hp[0], hb = hp[1];
        float hv[8] = {ha.x, ha.y, ha.z, ha.w, hb.x, hb.y, hb.z, hb.w};
        float accv[8];
#pragma unroll
        for (int tt = 0; tt < 8; tt++) {
            const float4* pq = (const float4*)&pp[tt][lane * 8];
            float4 pa = pq[0], pb = pq[1];
            float pv[8] = {pa.x, pa.y, pa.z, pa.w, pb.x, pb.y, pb.z, pb.w};
            float s = 0.f;
#pragma unroll
            for (int u = 0; u < 8; u++)
                s = fmaf(tanh_fast(hv[u] + pv[u]), wsr[u], s);
            accv[tt] = s;
        }
#pragma unroll
        for (int off = 16; off; off >>= 1)
#pragma unroll
            for (int tt = 0; tt < 8; tt++)
                accv[tt] += __shfl_xor_sync(0xffffffffu, accv[tt], off);
        if (lane < 8)
            scores[((long)(b * 512 + t0 + lane)) * 512 + l] = accv[lane] + wsb;
    }
}

// ---------------- softmax ----------------
__global__ void __launch_bounds__(256) softmax_kernel(float* __restrict__ s) {
    int row = blockIdx.x * 8 + (threadIdx.x >> 5);
    int lane = threadIdx.x & 31;
    float* p = s + (long)row * 512;
    float v[16];
    float m = -1e30f;
#pragma unroll
    for (int u = 0; u < 16; u++) { v[u] = p[u * 32 + lane]; m = fmaxf(m, v[u]); }
#pragma unroll
    for (int off = 16; off; off >>= 1) m = fmaxf(m, __shfl_xor_sync(0xffffffffu, m, off));
    float sum = 0.f;
#pragma unroll
    for (int u = 0; u < 16; u++) { v[u] = __expf(v[u] - m); sum += v[u]; }
#pragma unroll
    for (int off = 16; off; off >>= 1) sum += __shfl_xor_sync(0xffffffffu, sum, off);
    float inv = 1.0f / sum;
#pragma unroll
    for (int u = 0; u < 16; u++) p[u * 32 + lane] = v[u] * inv;
}

// ---------------- init recurrence state ----------------
__global__ void init_kernel() {
    int i = blockIdx.x * blockDim.x + threadIdx.x;
    if (i < 2 * 2 * Hz * Bz) ((float*)g_ht)[i] = 0.f;
    if (i < 2) g_bar[i] = 0u;
}

// ---------------- recurrence: 128 blocks (2 dirs x 64), 128 thr, warp=j lane=b ----
// h layout (smem + global): idx(k,b) = (k>>1)*64 + b*2 + (k&1)
__global__ void __launch_bounds__(128, 1) recur_kernel(
    const float* __restrict__ Whh_l, const float* __restrict__ bhh_l,
    const float* __restrict__ Whh_r, const float* __restrict__ bhh_r,
    float* __restrict__ out)
{
    __shared__ float ht[Hz * Bz];          // 32KB, pair-interleaved
    __shared__ float wsm[4 * 3 * 256];     // [jl][g][k], 12KB

    int dir   = blockIdx.x >> 6;
    int slice = blockIdx.x & 63;
    int tid   = threadIdx.x;
    int warp  = tid >> 5, lane = tid & 31;
    int j = slice * 4 + warp;

    const float* Whh = dir ? Whh_r : Whh_l;
    const float* bhh = dir ? bhh_r : bhh_l;
    const float* giT = dir ? g_girT : g_gilT;

    for (int idx = tid; idx < 3072; idx += 128) {
        int jl  = idx / 768;
        int rem = idx - jl * 768;
        int g   = rem >> 8;
        int k   = rem & 255;
        wsm[idx] = Whh[((g << 8) + slice * 4 + jl) * 256 + k];
    }
    float br = bhh[j], bz = bhh[j + 256], bn = bhh[j + 512];
    const float* wp = &wsm[warp * 768];

    unsigned* bar = &g_bar[dir];
    int hpidx = (j >> 1) * 64 + lane * 2 + (j & 1);

    for (int s = 0; s < 512; s++) {
        int t = dir ? (511 - s) : s;
        const float4* hsrc = (const float4*)(&g_ht[dir][s & 1][0]);
#pragma unroll
        for (int i = 0; i < 16; i++)
            ((float4*)ht)[tid + i * 128] = __ldcg(&hsrc[tid + i * 128]);
        __syncthreads();

        ull sr2a = 0, sr2b = 0, sz2a = 0, sz2b = 0, sn2a = 0, sn2b = 0;
#pragma unroll 8
        for (int k = 0; k < 256; k += 4) {
            ull h01 = *(const ull*)&ht[(k >> 1) * 64 + lane * 2];        // (h_k, h_k+1)
            ull h23 = *(const ull*)&ht[(k >> 1) * 64 + 64 + lane * 2];   // (h_k+2, h_k+3)
            ulonglong2 wr = *(const ulonglong2*)(wp + k);
            ulonglong2 wz = *(const ulonglong2*)(wp + 256 + k);
            ulonglong2 wn = *(const ulonglong2*)(wp + 512 + k);
            ffma2(sr2a, wr.x, h01); ffma2(sr2b, wr.y, h23);
            ffma2(sz2a, wz.x, h01); ffma2(sz2b, wz.y, h23);
            ffma2(sn2a, wn.x, h01); ffma2(sn2b, wn.y, h23);
        }
        float2 u0 = unp2(sr2a), u1 = unp2(sr2b);
        float sr = (u0.x + u0.y) + (u1.x + u1.y);
        float2 v0 = unp2(sz2a), v1 = unp2(sz2b);
        float sz = (v0.x + v0.y) + (v1.x + v1.y);
        float2 w0 = unp2(sn2a), w1 = unp2(sn2b);
        float sn = (w0.x + w0.y) + (w1.x + w1.y);

        long gbase = ((long)t * 768 + j) * 32 + lane;
        float gr_ = __ldg(giT + gbase);
        float gz_ = __ldg(giT + gbase + 256 * 32);
        float gn_ = __ldg(giT + gbase + 512 * 32);
        float hprev = ht[hpidx];
        float r = sigmoidf_(gr_ + br + sr);
        float z = sigmoidf_(gz_ + bz + sz);
        float n = tanh_fast(gn_ + r * (bn + sn));
        float hnew = (1.0f - z) * n + z * hprev;
        __stcg(&g_ht[dir][(s + 1) & 1][hpidx], hnew);
        out[((long)(lane * 512 + t)) * 512 + dir * 256 + j] = hnew;

        __syncthreads();
        if (tid == 0) {
            red_release_add(bar, 1u);
            unsigned target = 64u * (unsigned)(s + 1);
            while (ld_acq(bar) < target) { }
        }
        __syncthreads();
    }
}

// ---------------- host launcher ----------------
extern "C" void kernel_launch(void* const* d_in, const int* in_sizes, int n_in,
                              void* d_out, int out_size) {
    const float* P     = (const float*)d_in[0];
    const float* wq_w  = (const float*)d_in[1];
    const float* wq_b  = (const float*)d_in[2];
    const float* wp_w  = (const float*)d_in[3];
    const float* wp_b  = (const float*)d_in[4];
    const float* ws_w  = (const float*)d_in[5];
    const float* ws_b  = (const float*)d_in[6];
    const float* wg_w  = (const float*)d_in[7];
    const float* wg_b  = (const float*)d_in[8];
    const float* Wih_l = (const float*)d_in[9];
    const float* Whh_l = (const float*)d_in[10];
    const float* bih_l = (const float*)d_in[11];
    const float* bhh_l = (const float*)d_in[12];
    const float* Wih_r = (const float*)d_in[13];
    const float* Whh_r = (const float*)d_in[14];
    const float* bih_r = (const float*)d_in[15];
    const float* bhh_r = (const float*)d_in[16];
    float* out = (float*)d_out;

    float *pHq, *pPp, *pScores, *pPC, *pCg, *pGilT, *pGirT;
    cudaGetSymbolAddress((void**)&pHq, g_Hq);
    cudaGetSymbolAddress((void**)&pPp, g_Pp);
    cudaGetSymbolAddress((void**)&pScores, g_scores);
    cudaGetSymbolAddress((void**)&pPC, g_PC);
    cudaGetSymbolAddress((void**)&pCg, g_Cg);
    cudaGetSymbolAddress((void**)&pGilT, g_gilT);
    cudaGetSymbolAddress((void**)&pGirT, g_girT);

    // Phase A (SIMT f32x2 GEMMs)
    sgemm2_kernel<1,0><<<dim3(2,128,1), 256>>>(P, wq_w, wq_b, nullptr, pHq,
        ML, 256, 256, 0, 0, 0, 256, 0);
    sgemm2_kernel<1,0><<<dim3(2,128,1), 256>>>(P, wp_w, wp_b, nullptr, pPp,
        ML, 256, 256, 0, 0, 0, 256, 0);
    copyP_kernel<<<ML*256/4/256, 256>>>(P, pPC);
    scores_kernel<<<dim3(64,32), 256>>>(pHq, pPp, ws_w, ws_b, pScores);
    softmax_kernel<<<ML/8, 256>>>(pScores);
    // context per-b: C = attn @ P -> PC[:, 256:512]
    sgemm2_kernel<0,2><<<dim3(2,4,32), 256>>>(pScores, P, nullptr, nullptr, pPC,
        512, 256, 512, (long)512*512, (long)512*256, (long)512*512, 512, 256);
    // gate: Cg = sigmoid(PC @ wg^T + b) * C
    sgemm2_kernel<1,1><<<dim3(2,128,1), 256>>>(pPC, wg_w, wg_b, pPC, pCg,
        ML, 256, 512, 0, 0, 0, 256, 0);
    // GRU input projections -> transposed giT layout
    sgemm2_kernel<1,3><<<dim3(6,128,1), 256>>>(pCg, Wih_l, bih_l, nullptr, pGilT,
        ML, 768, 256, 0, 0, 0, 0, 0);
    sgemm2_kernel<1,3><<<dim3(6,128,1), 256>>>(pCg, Wih_r, bih_r, nullptr, pGirT,
        ML, 768, 256, 0, 0, 0, 0, 0);

    // Phase B
    init_kernel<<<128, 256>>>();
    recur_kernel<<<128, 128>>>(Whh_l, bhh_l, Whh_r, bhh_r, out);
}